// round 1
// baseline (speedup 1.0000x reference)
#include <cuda_runtime.h>
#include <cstdint>

#define HW      (256 * 256)
#define CCH     64
#define NPIX    (16 * HW)            // 1,048,576 pixels
#define NTOT    (16 * CCH * HW)      // 67,108,864 elements

// ---------------- device scratch (allocation-free: static device globals) ----
__device__ float    g_bufA[NTOT];
__device__ float    g_bufB[NTOT];
__device__ unsigned g_amax[4];        // abs-max bits of: x, y1, y3, y4
__device__ float    g_wscale[4];      // scales of: w_p1, w_f1, w_p2, w_f2
__device__ int      g_qwp[2][64 * 16];  // packed int8 pointwise weights [co][ci/4]
__device__ float    g_qwf[2][64 * 9];   // quantized (full fp value) depthwise weights

// ---------------- prep: weight quantization + amax reset ---------------------
__global__ void k_prep(const float* __restrict__ wp1, const float* __restrict__ wf1,
                       const float* __restrict__ wp2, const float* __restrict__ wf2)
{
    int b = blockIdx.x;   // 0:wp1 1:wf1 2:wp2 3:wf2
    const float* w = (b == 0) ? wp1 : (b == 1) ? wf1 : (b == 2) ? wp2 : wf2;
    int n = (b & 1) ? 576 : 4096;

    __shared__ float red[256];
    float m = 0.f;
    for (int i = threadIdx.x; i < n; i += 256) m = fmaxf(m, fabsf(w[i]));
    red[threadIdx.x] = m;
    __syncthreads();
    for (int s = 128; s > 0; s >>= 1) {
        if (threadIdx.x < s) red[threadIdx.x] = fmaxf(red[threadIdx.x], red[threadIdx.x + s]);
        __syncthreads();
    }
    __shared__ float s_scale;
    if (threadIdx.x == 0) {
        float sc = red[0] / 7.0f + 1e-12f;
        g_wscale[b] = sc;
        s_scale = sc;
        if (b == 0) { g_amax[0] = 0u; g_amax[1] = 0u; g_amax[2] = 0u; g_amax[3] = 0u; }
    }
    __syncthreads();
    float sc = s_scale;

    if (b & 1) {
        // depthwise: store quantized full fp value (exact division: matches jnp.round(t/scale))
        for (int i = threadIdx.x; i < 576; i += 256) {
            float q = fminf(fmaxf(rintf(w[i] / sc), -7.f), 7.f) * sc;
            g_qwf[b >> 1][i] = q;
        }
    } else {
        // pointwise: pack 4x int8 per word
        for (int i = threadIdx.x; i < 1024; i += 256) {
            int word = 0;
            #pragma unroll
            for (int j = 0; j < 4; j++) {
                float q = fminf(fmaxf(rintf(w[i * 4 + j] / sc), -7.f), 7.f);
                int qi = (int)q;
                word |= (qi & 0xFF) << (8 * j);
            }
            g_qwp[b >> 1][i] = word;
        }
    }
}

// ---------------- abs-max of x ----------------------------------------------
__global__ void __launch_bounds__(256) k_absmax(const float4* __restrict__ x, int nvec)
{
    float m = 0.f;
    for (int i = blockIdx.x * blockDim.x + threadIdx.x; i < nvec; i += gridDim.x * blockDim.x) {
        float4 v = x[i];
        m = fmaxf(m, fmaxf(fmaxf(fabsf(v.x), fabsf(v.y)), fmaxf(fabsf(v.z), fabsf(v.w))));
    }
    #pragma unroll
    for (int off = 16; off; off >>= 1) m = fmaxf(m, __shfl_xor_sync(0xFFFFFFFFu, m, off));
    __shared__ float wm[8];
    int lane = threadIdx.x & 31, wid = threadIdx.x >> 5;
    if (lane == 0) wm[wid] = m;
    __syncthreads();
    if (threadIdx.x == 0) {
        float mm = wm[0];
        #pragma unroll
        for (int i = 1; i < 8; i++) mm = fmaxf(mm, wm[i]);
        atomicMax(&g_amax[0], __float_as_uint(mm));
    }
}

// ---------------- pointwise 1x1 conv (dp4a int8 x int4) + fused out abs-max --
// in_sel: 0 = external x, 1 = bufA, 2 = bufB ; out_sel: 1 = bufA, 2 = bufB
// which: 0 -> w_p1 (amax_in 0, amax_out 1) ; 1 -> w_p2 (amax_in 2, amax_out 3)
__global__ void __launch_bounds__(256) k_pw(const float* __restrict__ xext,
                                            int in_sel, int out_sel, int which)
{
    const float* in  = (in_sel == 0) ? xext : (in_sel == 1) ? g_bufA : g_bufB;
    float*       out = (out_sel == 1) ? g_bufA : g_bufB;
    const int*   qw  = g_qwp[which];
    const int amax_in  = which * 2;
    const int amax_out = amax_in + 1;

    __shared__ __align__(16) int ws[1024];
    for (int i = threadIdx.x; i < 1024; i += 256) ws[i] = qw[i];
    __syncthreads();

    float in_max = __uint_as_float(g_amax[amax_in]);
    float s_in = in_max * (1.0f / 127.0f) + 1e-12f;
    float inv  = 1.0f / s_in;
    float osc  = s_in * g_wscale[which * 2];

    int p  = blockIdx.x * 256 + threadIdx.x;   // < NPIX
    int b  = p >> 16;
    int hw = p & 0xFFFF;
    const float* ip = in  + (unsigned)(b * CCH) * HW + hw;
    float*       op = out + (unsigned)(b * CCH) * HW + hw;

    // load + quantize + pack 64 input channels -> 16 int8x4 words
    int xq[16];
    #pragma unroll
    for (int k = 0; k < 16; k++) {
        int wv = 0;
        #pragma unroll
        for (int j = 0; j < 4; j++) {
            float v = ip[(unsigned)(4 * k + j) * HW];
            int qi = __float2int_rn(v * inv);
            qi = max(-127, min(127, qi));
            wv |= (qi & 0xFF) << (8 * j);
        }
        xq[k] = wv;
    }

    float lmax = 0.f;
    #pragma unroll 2
    for (int co = 0; co < 64; co++) {
        int acc = 0;
        #pragma unroll
        for (int k4 = 0; k4 < 4; k4++) {
            int4 w4 = *reinterpret_cast<const int4*>(&ws[co * 16 + k4 * 4]);
            acc = __dp4a(w4.x, xq[4 * k4 + 0], acc);
            acc = __dp4a(w4.y, xq[4 * k4 + 1], acc);
            acc = __dp4a(w4.z, xq[4 * k4 + 2], acc);
            acc = __dp4a(w4.w, xq[4 * k4 + 3], acc);
        }
        float y = (float)acc * osc;
        lmax = fmaxf(lmax, fabsf(y));
        op[(unsigned)co * HW] = y;
    }

    #pragma unroll
    for (int off = 16; off; off >>= 1) lmax = fmaxf(lmax, __shfl_xor_sync(0xFFFFFFFFu, lmax, off));
    __shared__ float wm[8];
    int lane = threadIdx.x & 31, wid = threadIdx.x >> 5;
    if (lane == 0) wm[wid] = lmax;
    __syncthreads();
    if (threadIdx.x == 0) {
        float mm = wm[0];
        #pragma unroll
        for (int i = 1; i < 8; i++) mm = fmaxf(mm, wm[i]);
        atomicMax(&g_amax[amax_out], __float_as_uint(mm));
    }
}

// ---------------- depthwise 3x3 + PReLU (+residual) + optional fused abs-max -
// which: 0 -> w_f1, amax_in=1, fused amax_out=2, no residual
//        1 -> w_f2, amax_in=3, residual add of xres, no amax out
// in_sel: 1 = bufA, 2 = bufB ; out_sel: 1 = bufA, 2 = bufB, 3 = dout
__global__ void __launch_bounds__(256) k_dw(const float* __restrict__ xres,
                                            float* __restrict__ dout,
                                            const float* __restrict__ alpha,
                                            int in_sel, int out_sel, int which)
{
    const float* in  = (in_sel == 1) ? g_bufA : g_bufB;
    float*       out = (out_sel == 3) ? dout : ((out_sel == 1) ? g_bufA : g_bufB);

    int bc = blockIdx.x >> 5;      // b*64 + c   (0..1023)
    int ht = blockIdx.x & 31;
    int c  = bc & 63;
    int h0 = ht * 8;

    float in_max = __uint_as_float(g_amax[which == 0 ? 1 : 3]);
    float s_in = in_max * (1.0f / 127.0f) + 1e-12f;
    float inv  = 1.0f / s_in;

    __shared__ float tile[10][264];
    const float* base = in + (unsigned)bc * HW;
    for (int i = threadIdx.x; i < 10 * 258; i += 256) {
        int r  = i / 258;
        int wi = i % 258 - 1;
        int hh = h0 - 1 + r;
        float v = 0.f;
        if (hh >= 0 && hh < 256 && wi >= 0 && wi < 256) v = base[hh * 256 + wi];
        tile[r][wi + 1] = fminf(fmaxf(rintf(v * inv), -127.f), 127.f);
    }
    float wf[9];
    #pragma unroll
    for (int j = 0; j < 9; j++) wf[j] = g_qwf[which][c * 9 + j];
    float a = alpha[c];
    __syncthreads();

    int w = threadIdx.x;
    float lmax = 0.f;
    #pragma unroll
    for (int r = 0; r < 8; r++) {
        float acc = 0.f;
        #pragma unroll
        for (int dr = 0; dr < 3; dr++)
            #pragma unroll
            for (int dc = 0; dc < 3; dc++)
                acc += tile[r + dr][w + dc] * wf[dr * 3 + dc];
        float y = acc * s_in;
        y = (y > 0.f) ? y : a * y;
        int idx = (h0 + r) * 256 + w;
        if (which == 0) {
            lmax = fmaxf(lmax, fabsf(y));
        } else {
            y += xres[(unsigned)bc * HW + idx];
        }
        out[(unsigned)bc * HW + idx] = y;
    }

    if (which == 0) {
        #pragma unroll
        for (int off = 16; off; off >>= 1) lmax = fmaxf(lmax, __shfl_xor_sync(0xFFFFFFFFu, lmax, off));
        __shared__ float wm[8];
        int lane = threadIdx.x & 31, wid = threadIdx.x >> 5;
        if (lane == 0) wm[wid] = lmax;
        __syncthreads();
        if (threadIdx.x == 0) {
            float mm = wm[0];
            #pragma unroll
            for (int i = 1; i < 8; i++) mm = fmaxf(mm, wm[i]);
            atomicMax(&g_amax[2], __float_as_uint(mm));
        }
    }
}

// ---------------- launch ------------------------------------------------------
extern "C" void kernel_launch(void* const* d_in, const int* in_sizes, int n_in,
                              void* d_out, int out_size)
{
    const float* x      = (const float*)d_in[0];
    const float* w_p1   = (const float*)d_in[1];
    const float* w_f1   = (const float*)d_in[2];
    const float* w_p2   = (const float*)d_in[3];
    const float* w_f2   = (const float*)d_in[4];
    const float* alpha1 = (const float*)d_in[5];
    const float* alpha2 = (const float*)d_in[6];
    float* out = (float*)d_out;

    // weight quant + amax reset
    k_prep<<<4, 256>>>(w_p1, w_f1, w_p2, w_f2);

    // abs-max of x
    k_absmax<<<2048, 256>>>((const float4*)x, NTOT / 4);

    // stage 1: pointwise conv1 (x -> bufA), fused absmax(y1)
    k_pw<<<NPIX / 256, 256>>>(x, /*in_sel=*/0, /*out_sel=*/1, /*which=*/0);

    // stage 2: depthwise conv1 + PReLU (bufA -> bufB), fused absmax(y3)
    k_dw<<<16 * 64 * 32, 256>>>(nullptr, nullptr, alpha1, /*in_sel=*/1, /*out_sel=*/2, /*which=*/0);

    // stage 3: pointwise conv2 (bufB -> bufA), fused absmax(y4)
    k_pw<<<NPIX / 256, 256>>>(nullptr, /*in_sel=*/2, /*out_sel=*/1, /*which=*/1);

    // stage 4: depthwise conv2 + PReLU + residual (bufA -> out)
    k_dw<<<16 * 64 * 32, 256>>>(x, out, alpha2, /*in_sel=*/1, /*out_sel=*/3, /*which=*/1);
}

// round 2
// speedup vs baseline: 1.5297x; 1.5297x over previous
#include <cuda_runtime.h>
#include <cuda_fp16.h>
#include <cstdint>

#define HW    65536
#define CCH   64
#define NPIX  (16 * HW)            // 1,048,576 pixels
#define NTOT  (16 * CCH * HW)      // 67,108,864 elements

// ---------------- device scratch (allocation-free) ---------------------------
__device__ __half   g_bufA[NTOT];
__device__ __half   g_bufB[NTOT];
__device__ unsigned g_amax[4];        // abs-max bits of: x, y1, y3, y4
__device__ float    g_wscale[4];      // scales of: w_p1, w_f1, w_p2, w_f2
__device__ int      g_qwp[2][1024];   // packed int8 pointwise weights [co][ci/4]
__device__ float    g_qwf[2][576];    // quantized depthwise weights (fp value)

// ---------------- prep: weight quantization + amax reset ---------------------
__global__ void k_prep(const float* __restrict__ wp1, const float* __restrict__ wf1,
                       const float* __restrict__ wp2, const float* __restrict__ wf2)
{
    int b = blockIdx.x;   // 0:wp1 1:wf1 2:wp2 3:wf2
    const float* w = (b == 0) ? wp1 : (b == 1) ? wf1 : (b == 2) ? wp2 : wf2;
    int n = (b & 1) ? 576 : 4096;

    __shared__ float red[256];
    float m = 0.f;
    for (int i = threadIdx.x; i < n; i += 256) m = fmaxf(m, fabsf(w[i]));
    red[threadIdx.x] = m;
    __syncthreads();
    for (int s = 128; s > 0; s >>= 1) {
        if (threadIdx.x < s) red[threadIdx.x] = fmaxf(red[threadIdx.x], red[threadIdx.x + s]);
        __syncthreads();
    }
    __shared__ float s_scale;
    if (threadIdx.x == 0) {
        float sc = red[0] / 7.0f + 1e-12f;
        g_wscale[b] = sc;
        s_scale = sc;
        if (b == 0) { g_amax[0] = 0u; g_amax[1] = 0u; g_amax[2] = 0u; g_amax[3] = 0u; }
    }
    __syncthreads();
    float sc = s_scale;

    if (b & 1) {
        for (int i = threadIdx.x; i < 576; i += 256) {
            float q = fminf(fmaxf(rintf(w[i] / sc), -7.f), 7.f) * sc;
            g_qwf[b >> 1][i] = q;
        }
    } else {
        for (int i = threadIdx.x; i < 1024; i += 256) {
            int word = 0;
            #pragma unroll
            for (int j = 0; j < 4; j++) {
                float q = fminf(fmaxf(rintf(w[i * 4 + j] / sc), -7.f), 7.f);
                int qi = (int)q;
                word |= (qi & 0xFF) << (8 * j);
            }
            g_qwp[b >> 1][i] = word;
        }
    }
}

// ---------------- abs-max of x ----------------------------------------------
__global__ void __launch_bounds__(256) k_absmax(const float4* __restrict__ x, int nvec)
{
    float m = 0.f;
    for (int i = blockIdx.x * blockDim.x + threadIdx.x; i < nvec; i += gridDim.x * blockDim.x) {
        float4 v = x[i];
        m = fmaxf(m, fmaxf(fmaxf(fabsf(v.x), fabsf(v.y)), fmaxf(fabsf(v.z), fabsf(v.w))));
    }
    #pragma unroll
    for (int off = 16; off; off >>= 1) m = fmaxf(m, __shfl_xor_sync(0xFFFFFFFFu, m, off));
    __shared__ float wm[8];
    int lane = threadIdx.x & 31, wid = threadIdx.x >> 5;
    if (lane == 0) wm[wid] = m;
    __syncthreads();
    if (threadIdx.x == 0) {
        float mm = wm[0];
        #pragma unroll
        for (int i = 1; i < 8; i++) mm = fmaxf(mm, wm[i]);
        atomicMax(&g_amax[0], __float_as_uint(mm));
    }
}

// ---------------- pointwise 1x1 conv (dp4a) + fused out abs-max --------------
// WHICH 0: in = x (fp32),   out = bufA (half), amax 0 -> 1
// WHICH 1: in = bufB (half), out = bufA (half), amax 2 -> 3
template<int WHICH>
__global__ void __launch_bounds__(256) k_pw(const float* __restrict__ x32)
{
    __shared__ __align__(16) int ws[1024];
    for (int i = threadIdx.x; i < 1024; i += 256) ws[i] = g_qwp[WHICH][i];
    __syncthreads();

    float in_max = __uint_as_float(g_amax[WHICH * 2]);
    float s_in = in_max * (1.0f / 127.0f) + 1e-12f;
    float inv  = 1.0f / s_in;
    float osc  = s_in * g_wscale[WHICH * 2];

    int p  = blockIdx.x * 256 + threadIdx.x;   // < NPIX
    int b  = p >> 16;
    int hw = p & 0xFFFF;
    unsigned base = (unsigned)(b * CCH) * HW + hw;

    // load + quantize + pack 64 input channels -> 16 int8x4 words (no clamp needed)
    int xq[16];
    #pragma unroll
    for (int k = 0; k < 16; k++) {
        int wv = 0;
        #pragma unroll
        for (int j = 0; j < 4; j++) {
            float v;
            if (WHICH == 0) v = x32[base + (unsigned)(4 * k + j) * HW];
            else            v = __half2float(g_bufB[base + (unsigned)(4 * k + j) * HW]);
            int qi = __float2int_rn(v * inv);
            wv |= (qi & 0xFF) << (8 * j);
        }
        xq[k] = wv;
    }

    float lmax = 0.f;
    #pragma unroll 2
    for (int co = 0; co < 64; co++) {
        int acc = 0;
        #pragma unroll
        for (int k4 = 0; k4 < 4; k4++) {
            int4 w4 = *reinterpret_cast<const int4*>(&ws[co * 16 + k4 * 4]);
            acc = __dp4a(w4.x, xq[4 * k4 + 0], acc);
            acc = __dp4a(w4.y, xq[4 * k4 + 1], acc);
            acc = __dp4a(w4.z, xq[4 * k4 + 2], acc);
            acc = __dp4a(w4.w, xq[4 * k4 + 3], acc);
        }
        float y = (float)acc * osc;
        lmax = fmaxf(lmax, fabsf(y));
        g_bufA[base + (unsigned)co * HW] = __float2half(y);
    }

    #pragma unroll
    for (int off = 16; off; off >>= 1) lmax = fmaxf(lmax, __shfl_xor_sync(0xFFFFFFFFu, lmax, off));
    __shared__ float wm[8];
    int lane = threadIdx.x & 31, wid = threadIdx.x >> 5;
    if (lane == 0) wm[wid] = lmax;
    __syncthreads();
    if (threadIdx.x == 0) {
        float mm = wm[0];
        #pragma unroll
        for (int i = 1; i < 8; i++) mm = fmaxf(mm, wm[i]);
        atomicMax(&g_amax[WHICH * 2 + 1], __float_as_uint(mm));
    }
}

// ---------------- depthwise 3x3 + PReLU (+residual), register sliding window -
// WHICH 0: in bufA(half) -> out bufB(half), amax_in [1], fused amax_out [2]
// WHICH 1: in bufA(half) -> out dout(fp32) + residual xres, amax_in [3]
// Block: 256 thr = 64 col-groups (4 cols each) x 4 row-groups (8 rows each).
// Grid: 1024 (b*c) x 8 strips of 32 rows.
template<int WHICH>
__global__ void __launch_bounds__(256) k_dw(const float* __restrict__ xres,
                                            float* __restrict__ dout,
                                            const float* __restrict__ alpha)
{
    int bc    = blockIdx.x >> 3;     // 0..1023
    int strip = blockIdx.x & 7;
    int c  = bc & 63;
    int tx = threadIdx.x & 63;
    int ty = threadIdx.x >> 6;
    int lane = threadIdx.x & 31;
    int rbase = strip * 32 + ty * 8;
    int col0  = tx * 4;

    float in_max = __uint_as_float(g_amax[WHICH == 0 ? 1 : 3]);
    float s_in = in_max * (1.0f / 127.0f) + 1e-12f;
    float inv  = 1.0f / s_in;

    float wf[9];
    #pragma unroll
    for (int j = 0; j < 9; j++) wf[j] = g_qwf[WHICH][c * 9 + j];
    float a = alpha[c];

    const __half* in = g_bufA + (unsigned)bc * HW;
    float accT[4] = {0.f, 0.f, 0.f, 0.f};
    float accM[4] = {0.f, 0.f, 0.f, 0.f};
    float lmax = 0.f;

    for (int k = 0; k < 10; k++) {
        int rr = rbase - 1 + k;          // input row (warp-uniform)
        float q0 = 0.f, q1 = 0.f, q2 = 0.f, q3 = 0.f, qL = 0.f, qR = 0.f;
        if (rr >= 0 && rr < 256) {
            const __half* rp = in + rr * 256 + col0;
            uint2 raw = *reinterpret_cast<const uint2*>(rp);
            float2 f01 = __half22float2(*reinterpret_cast<__half2*>(&raw.x));
            float2 f23 = __half22float2(*reinterpret_cast<__half2*>(&raw.y));
            q0 = rintf(f01.x * inv); q1 = rintf(f01.y * inv);
            q2 = rintf(f23.x * inv); q3 = rintf(f23.y * inv);
            qL = __shfl_up_sync(0xFFFFFFFFu, q3, 1);
            qR = __shfl_down_sync(0xFFFFFFFFu, q0, 1);
            if (lane == 0)  qL = (tx == 0)  ? 0.f : rintf(__half2float(rp[-1]) * inv);
            if (lane == 31) qR = (tx == 63) ? 0.f : rintf(__half2float(rp[4]) * inv);
        }
        float L[4] = {qL, q0, q1, q2};
        float M[4] = {q0, q1, q2, q3};
        float R[4] = {q1, q2, q3, qR};

        float s0[4], s1[4], s2[4];
        #pragma unroll
        for (int j = 0; j < 4; j++) {
            s0[j] = wf[0] * L[j] + wf[1] * M[j] + wf[2] * R[j];
            s1[j] = wf[3] * L[j] + wf[4] * M[j] + wf[5] * R[j];
            s2[j] = wf[6] * L[j] + wf[7] * M[j] + wf[8] * R[j];
        }

        if (k >= 2) {
            int ro = rbase + k - 2;
            float y[4];
            #pragma unroll
            for (int j = 0; j < 4; j++) {
                float v = (accM[j] + s2[j]) * s_in;
                y[j] = (v > 0.f) ? v : a * v;
            }
            unsigned off = (unsigned)bc * HW + (unsigned)(ro * 256 + col0);
            if (WHICH == 0) {
                #pragma unroll
                for (int j = 0; j < 4; j++) lmax = fmaxf(lmax, fabsf(y[j]));
                __half2 h01 = __floats2half2_rn(y[0], y[1]);
                __half2 h23 = __floats2half2_rn(y[2], y[3]);
                uint2 st;
                st.x = *reinterpret_cast<unsigned*>(&h01);
                st.y = *reinterpret_cast<unsigned*>(&h23);
                *reinterpret_cast<uint2*>(g_bufB + off) = st;
            } else {
                float4 r4 = *reinterpret_cast<const float4*>(xres + off);
                float4 o;
                o.x = y[0] + r4.x; o.y = y[1] + r4.y;
                o.z = y[2] + r4.z; o.w = y[3] + r4.w;
                *reinterpret_cast<float4*>(dout + off) = o;
            }
        }
        #pragma unroll
        for (int j = 0; j < 4; j++) { accM[j] = accT[j] + s1[j]; accT[j] = s0[j]; }
    }

    if (WHICH == 0) {
        #pragma unroll
        for (int off = 16; off; off >>= 1) lmax = fmaxf(lmax, __shfl_xor_sync(0xFFFFFFFFu, lmax, off));
        __shared__ float wm[8];
        if (lane == 0) wm[threadIdx.x >> 5] = lmax;
        __syncthreads();
        if (threadIdx.x == 0) {
            float mm = wm[0];
            #pragma unroll
            for (int i = 1; i < 8; i++) mm = fmaxf(mm, wm[i]);
            atomicMax(&g_amax[2], __float_as_uint(mm));
        }
    }
}

// ---------------- launch ------------------------------------------------------
extern "C" void kernel_launch(void* const* d_in, const int* in_sizes, int n_in,
                              void* d_out, int out_size)
{
    const float* x      = (const float*)d_in[0];
    const float* w_p1   = (const float*)d_in[1];
    const float* w_f1   = (const float*)d_in[2];
    const float* w_p2   = (const float*)d_in[3];
    const float* w_f2   = (const float*)d_in[4];
    const float* alpha1 = (const float*)d_in[5];
    const float* alpha2 = (const float*)d_in[6];
    float* out = (float*)d_out;

    k_prep<<<4, 256>>>(w_p1, w_f1, w_p2, w_f2);
    k_absmax<<<2048, 256>>>((const float4*)x, NTOT / 4);

    k_pw<0><<<NPIX / 256, 256>>>(x);                    // x -> bufA, amax y1
    k_dw<0><<<8192, 256>>>(nullptr, nullptr, alpha1);   // bufA -> bufB, amax y3
    k_pw<1><<<NPIX / 256, 256>>>(nullptr);              // bufB -> bufA, amax y4
    k_dw<1><<<8192, 256>>>(x, out, alpha2);             // bufA -> out (+x)
}

// round 3
// speedup vs baseline: 1.8972x; 1.2403x over previous
#include <cuda_runtime.h>
#include <cuda_fp16.h>
#include <cstdint>

#define HW    65536
#define CCH   64
#define NPIX  (16 * HW)            // 1,048,576 pixels
#define NTOT  (16 * CCH * HW)      // 67,108,864 elements

// ---------------- device scratch (allocation-free) ---------------------------
__device__ __half   g_bufA[NTOT];
__device__ __half   g_bufB[NTOT];
__device__ unsigned g_amax[4];        // abs-max bits of: x, y1, y3, y4
__device__ float    g_wscale[4];      // scales of: w_p1, w_f1, w_p2, w_f2
__device__ int      g_qwp[2][1024];   // packed int8 pointwise weights [co][ci/4]
__device__ float    g_qwf[2][576];    // quantized depthwise weights (fp value)

// ---------------- prep: weight quantization + amax reset ---------------------
__global__ void k_prep(const float* __restrict__ wp1, const float* __restrict__ wf1,
                       const float* __restrict__ wp2, const float* __restrict__ wf2)
{
    int b = blockIdx.x;   // 0:wp1 1:wf1 2:wp2 3:wf2
    const float* w = (b == 0) ? wp1 : (b == 1) ? wf1 : (b == 2) ? wp2 : wf2;
    int n = (b & 1) ? 576 : 4096;

    __shared__ float red[256];
    float m = 0.f;
    for (int i = threadIdx.x; i < n; i += 256) m = fmaxf(m, fabsf(w[i]));
    red[threadIdx.x] = m;
    __syncthreads();
    for (int s = 128; s > 0; s >>= 1) {
        if (threadIdx.x < s) red[threadIdx.x] = fmaxf(red[threadIdx.x], red[threadIdx.x + s]);
        __syncthreads();
    }
    __shared__ float s_scale;
    if (threadIdx.x == 0) {
        float sc = red[0] / 7.0f + 1e-12f;
        g_wscale[b] = sc;
        s_scale = sc;
        if (b == 0) { g_amax[0] = 0u; g_amax[1] = 0u; g_amax[2] = 0u; g_amax[3] = 0u; }
    }
    __syncthreads();
    float sc = s_scale;

    if (b & 1) {
        for (int i = threadIdx.x; i < 576; i += 256) {
            float q = fminf(fmaxf(rintf(w[i] / sc), -7.f), 7.f) * sc;
            g_qwf[b >> 1][i] = q;
        }
    } else {
        for (int i = threadIdx.x; i < 1024; i += 256) {
            int word = 0;
            #pragma unroll
            for (int j = 0; j < 4; j++) {
                float q = fminf(fmaxf(rintf(w[i * 4 + j] / sc), -7.f), 7.f);
                int qi = (int)q;
                word |= (qi & 0xFF) << (8 * j);
            }
            g_qwp[b >> 1][i] = word;
        }
    }
}

// ---------------- abs-max of x ----------------------------------------------
__global__ void __launch_bounds__(256) k_absmax(const float4* __restrict__ x, int nvec)
{
    float m = 0.f;
    for (int i = blockIdx.x * blockDim.x + threadIdx.x; i < nvec; i += gridDim.x * blockDim.x) {
        float4 v = x[i];
        m = fmaxf(m, fmaxf(fmaxf(fabsf(v.x), fabsf(v.y)), fmaxf(fabsf(v.z), fabsf(v.w))));
    }
    #pragma unroll
    for (int off = 16; off; off >>= 1) m = fmaxf(m, __shfl_xor_sync(0xFFFFFFFFu, m, off));
    __shared__ float wm[8];
    int lane = threadIdx.x & 31, wid = threadIdx.x >> 5;
    if (lane == 0) wm[wid] = m;
    __syncthreads();
    if (threadIdx.x == 0) {
        float mm = wm[0];
        #pragma unroll
        for (int i = 1; i < 8; i++) mm = fmaxf(mm, wm[i]);
        atomicMax(&g_amax[0], __float_as_uint(mm));
    }
}

// ---------------- pointwise 1x1 conv (dp4a), 4 pixels/thread -----------------
// WHICH 0: in = x (fp32),   out = bufA (half), amax 0 -> 1
// WHICH 1: in = bufB (half), out = bufA (half), amax 2 -> 3
template<int WHICH>
__global__ void __launch_bounds__(128) k_pw(const float* __restrict__ x32)
{
    __shared__ __align__(16) int ws[1024];
    for (int i = threadIdx.x; i < 1024; i += 128) ws[i] = g_qwp[WHICH][i];
    __syncthreads();

    float in_max = __uint_as_float(g_amax[WHICH * 2]);
    float s_in = in_max * (1.0f / 127.0f) + 1e-12f;
    float inv  = 1.0f / s_in;
    float osc  = s_in * g_wscale[WHICH * 2];

    unsigned p  = (blockIdx.x * 128u + threadIdx.x) * 4u;   // first of 4 pixels
    unsigned b  = p >> 16;
    unsigned hw = p & 0xFFFFu;
    unsigned base = b * (CCH * HW) + hw;

    // quantize+pack 64 input channels for 4 pixels -> 4 x 16 int8x4 words
    int xq0[16], xq1[16], xq2[16], xq3[16];
    #pragma unroll
    for (int k = 0; k < 16; k++) {
        int w0 = 0, w1 = 0, w2 = 0, w3 = 0;
        #pragma unroll
        for (int j = 0; j < 4; j++) {
            unsigned ci = 4 * k + j;
            float v0, v1, v2, v3;
            if (WHICH == 0) {
                float4 v = *reinterpret_cast<const float4*>(x32 + base + ci * HW);
                v0 = v.x; v1 = v.y; v2 = v.z; v3 = v.w;
            } else {
                uint2 raw = *reinterpret_cast<const uint2*>(g_bufB + base + ci * HW);
                float2 f01 = __half22float2(*reinterpret_cast<__half2*>(&raw.x));
                float2 f23 = __half22float2(*reinterpret_cast<__half2*>(&raw.y));
                v0 = f01.x; v1 = f01.y; v2 = f23.x; v3 = f23.y;
            }
            w0 |= (__float2int_rn(v0 * inv) & 0xFF) << (8 * j);
            w1 |= (__float2int_rn(v1 * inv) & 0xFF) << (8 * j);
            w2 |= (__float2int_rn(v2 * inv) & 0xFF) << (8 * j);
            w3 |= (__float2int_rn(v3 * inv) & 0xFF) << (8 * j);
        }
        xq0[k] = w0; xq1[k] = w1; xq2[k] = w2; xq3[k] = w3;
    }

    float lmax = 0.f;
    #pragma unroll 2
    for (int co = 0; co < 64; co++) {
        int a0 = 0, a1 = 0, a2 = 0, a3 = 0;
        #pragma unroll
        for (int k4 = 0; k4 < 4; k4++) {
            int4 w4 = *reinterpret_cast<const int4*>(&ws[co * 16 + k4 * 4]);
            a0 = __dp4a(w4.x, xq0[4 * k4 + 0], a0);
            a0 = __dp4a(w4.y, xq0[4 * k4 + 1], a0);
            a0 = __dp4a(w4.z, xq0[4 * k4 + 2], a0);
            a0 = __dp4a(w4.w, xq0[4 * k4 + 3], a0);
            a1 = __dp4a(w4.x, xq1[4 * k4 + 0], a1);
            a1 = __dp4a(w4.y, xq1[4 * k4 + 1], a1);
            a1 = __dp4a(w4.z, xq1[4 * k4 + 2], a1);
            a1 = __dp4a(w4.w, xq1[4 * k4 + 3], a1);
            a2 = __dp4a(w4.x, xq2[4 * k4 + 0], a2);
            a2 = __dp4a(w4.y, xq2[4 * k4 + 1], a2);
            a2 = __dp4a(w4.z, xq2[4 * k4 + 2], a2);
            a2 = __dp4a(w4.w, xq2[4 * k4 + 3], a2);
            a3 = __dp4a(w4.x, xq3[4 * k4 + 0], a3);
            a3 = __dp4a(w4.y, xq3[4 * k4 + 1], a3);
            a3 = __dp4a(w4.z, xq3[4 * k4 + 2], a3);
            a3 = __dp4a(w4.w, xq3[4 * k4 + 3], a3);
        }
        float y0 = (float)a0 * osc;
        float y1 = (float)a1 * osc;
        float y2 = (float)a2 * osc;
        float y3 = (float)a3 * osc;
        lmax = fmaxf(lmax, fmaxf(fmaxf(fabsf(y0), fabsf(y1)), fmaxf(fabsf(y2), fabsf(y3))));
        __half2 h01 = __floats2half2_rn(y0, y1);
        __half2 h23 = __floats2half2_rn(y2, y3);
        uint2 st;
        st.x = *reinterpret_cast<unsigned*>(&h01);
        st.y = *reinterpret_cast<unsigned*>(&h23);
        *reinterpret_cast<uint2*>(g_bufA + base + (unsigned)co * HW) = st;
    }

    #pragma unroll
    for (int off = 16; off; off >>= 1) lmax = fmaxf(lmax, __shfl_xor_sync(0xFFFFFFFFu, lmax, off));
    __shared__ float wm[4];
    int lane = threadIdx.x & 31, wid = threadIdx.x >> 5;
    if (lane == 0) wm[wid] = lmax;
    __syncthreads();
    if (threadIdx.x == 0) {
        float mm = fmaxf(fmaxf(wm[0], wm[1]), fmaxf(wm[2], wm[3]));
        atomicMax(&g_amax[WHICH * 2 + 1], __float_as_uint(mm));
    }
}

// ---------------- depthwise 3x3 + PReLU (+residual), warp-per-row-span -------
// WHICH 0: bufA(half) -> bufB(half), amax_in [1], fused amax_out [2]
// WHICH 1: bufA(half) -> dout(fp32) + residual xres, amax_in [3]
// Block: 128 thr = 4 warps, each warp: 8 rows x 256 cols (8 cols/lane).
// Grid: 1024 (b*c) x 8 strips of 32 rows.
template<int WHICH>
__global__ void __launch_bounds__(128) k_dw(const float* __restrict__ xres,
                                            float* __restrict__ dout,
                                            const float* __restrict__ alpha)
{
    int bc    = blockIdx.x >> 3;     // 0..1023
    int strip = blockIdx.x & 7;
    int c     = bc & 63;
    int warp  = threadIdx.x >> 5;
    int lane  = threadIdx.x & 31;
    int rbase = strip * 32 + warp * 8;
    int col0  = lane * 8;

    float in_max = __uint_as_float(g_amax[WHICH == 0 ? 1 : 3]);
    float s_in = in_max * (1.0f / 127.0f) + 1e-12f;
    float inv  = 1.0f / s_in;

    float wf[9];
    #pragma unroll
    for (int j = 0; j < 9; j++) wf[j] = g_qwf[WHICH][c * 9 + j];
    float a = alpha[c];

    const __half* in = g_bufA + (unsigned)bc * HW;
    float accT[8], accM[8];
    #pragma unroll
    for (int j = 0; j < 8; j++) { accT[j] = 0.f; accM[j] = 0.f; }
    float lmax = 0.f;

    for (int k = 0; k < 10; k++) {
        int rr = rbase - 1 + k;          // warp-uniform input row
        float e[10];                     // [qL, q0..q7, qR]
        if (rr >= 0 && rr < 256) {
            uint4 raw = *reinterpret_cast<const uint4*>(in + rr * 256 + col0);
            float2 f0 = __half22float2(*reinterpret_cast<__half2*>(&raw.x));
            float2 f1 = __half22float2(*reinterpret_cast<__half2*>(&raw.y));
            float2 f2 = __half22float2(*reinterpret_cast<__half2*>(&raw.z));
            float2 f3 = __half22float2(*reinterpret_cast<__half2*>(&raw.w));
            e[1] = rintf(f0.x * inv); e[2] = rintf(f0.y * inv);
            e[3] = rintf(f1.x * inv); e[4] = rintf(f1.y * inv);
            e[5] = rintf(f2.x * inv); e[6] = rintf(f2.y * inv);
            e[7] = rintf(f3.x * inv); e[8] = rintf(f3.y * inv);
            float qL = __shfl_up_sync(0xFFFFFFFFu, e[8], 1);
            float qR = __shfl_down_sync(0xFFFFFFFFu, e[1], 1);
            e[0] = (lane == 0)  ? 0.f : qL;   // image left edge
            e[9] = (lane == 31) ? 0.f : qR;   // image right edge
        } else {
            #pragma unroll
            for (int j = 0; j < 10; j++) e[j] = 0.f;
        }

        float s0[8], s1[8], s2[8];
        #pragma unroll
        for (int j = 0; j < 8; j++) {
            float L = e[j], M = e[j + 1], R = e[j + 2];
            s0[j] = wf[0] * L + wf[1] * M + wf[2] * R;
            s1[j] = wf[3] * L + wf[4] * M + wf[5] * R;
            s2[j] = wf[6] * L + wf[7] * M + wf[8] * R;
        }

        if (k >= 2) {
            int ro = rbase + k - 2;
            unsigned off = (unsigned)bc * HW + (unsigned)(ro * 256 + col0);
            float y[8];
            #pragma unroll
            for (int j = 0; j < 8; j++) {
                float v = (accM[j] + s2[j]) * s_in;
                y[j] = (v > 0.f) ? v : a * v;
            }
            if (WHICH == 0) {
                #pragma unroll
                for (int j = 0; j < 8; j++) lmax = fmaxf(lmax, fabsf(y[j]));
                uint4 st;
                __half2 h0 = __floats2half2_rn(y[0], y[1]);
                __half2 h1 = __floats2half2_rn(y[2], y[3]);
                __half2 h2 = __floats2half2_rn(y[4], y[5]);
                __half2 h3 = __floats2half2_rn(y[6], y[7]);
                st.x = *reinterpret_cast<unsigned*>(&h0);
                st.y = *reinterpret_cast<unsigned*>(&h1);
                st.z = *reinterpret_cast<unsigned*>(&h2);
                st.w = *reinterpret_cast<unsigned*>(&h3);
                *reinterpret_cast<uint4*>(g_bufB + off) = st;
            } else {
                float4 r0 = *reinterpret_cast<const float4*>(xres + off);
                float4 r1 = *reinterpret_cast<const float4*>(xres + off + 4);
                float4 o0, o1;
                o0.x = y[0] + r0.x; o0.y = y[1] + r0.y;
                o0.z = y[2] + r0.z; o0.w = y[3] + r0.w;
                o1.x = y[4] + r1.x; o1.y = y[5] + r1.y;
                o1.z = y[6] + r1.z; o1.w = y[7] + r1.w;
                *reinterpret_cast<float4*>(dout + off)     = o0;
                *reinterpret_cast<float4*>(dout + off + 4) = o1;
            }
        }
        #pragma unroll
        for (int j = 0; j < 8; j++) { accM[j] = accT[j] + s1[j]; accT[j] = s0[j]; }
    }

    if (WHICH == 0) {
        #pragma unroll
        for (int off = 16; off; off >>= 1) lmax = fmaxf(lmax, __shfl_xor_sync(0xFFFFFFFFu, lmax, off));
        __shared__ float wm[4];
        if (lane == 0) wm[warp] = lmax;
        __syncthreads();
        if (threadIdx.x == 0) {
            float mm = fmaxf(fmaxf(wm[0], wm[1]), fmaxf(wm[2], wm[3]));
            atomicMax(&g_amax[2], __float_as_uint(mm));
        }
    }
}

// ---------------- launch ------------------------------------------------------
extern "C" void kernel_launch(void* const* d_in, const int* in_sizes, int n_in,
                              void* d_out, int out_size)
{
    const float* x      = (const float*)d_in[0];
    const float* w_p1   = (const float*)d_in[1];
    const float* w_f1   = (const float*)d_in[2];
    const float* w_p2   = (const float*)d_in[3];
    const float* w_f2   = (const float*)d_in[4];
    const float* alpha1 = (const float*)d_in[5];
    const float* alpha2 = (const float*)d_in[6];
    float* out = (float*)d_out;

    k_prep<<<4, 256>>>(w_p1, w_f1, w_p2, w_f2);
    k_absmax<<<2048, 256>>>((const float4*)x, NTOT / 4);

    k_pw<0><<<NPIX / 512, 128>>>(x);                    // x -> bufA, amax y1
    k_dw<0><<<8192, 128>>>(nullptr, nullptr, alpha1);   // bufA -> bufB, amax y3
    k_pw<1><<<NPIX / 512, 128>>>(nullptr);              // bufB -> bufA, amax y4
    k_dw<1><<<8192, 128>>>(x, out, alpha2);             // bufA -> out (+x)
}

// round 4
// speedup vs baseline: 2.0547x; 1.0830x over previous
#include <cuda_runtime.h>
#include <cuda_fp16.h>
#include <cstdint>

#define HW    65536
#define CCH   64
#define NPIX  (16 * HW)            // 1,048,576 pixels
#define NTOT  (16 * CCH * HW)      // 67,108,864 elements

// ---------------- device scratch (allocation-free) ---------------------------
__device__ __half   g_bufA[NTOT];
__device__ __half   g_bufB[NTOT];
__device__ unsigned g_amax[4];        // abs-max bits of: x, y1, y3, y4
__device__ float    g_wscale[4];      // scales of: w_p1, w_f1, w_p2, w_f2
__device__ int      g_qwp[2][1024];   // packed int8 pointwise weights [co][ci/4]
__device__ int      g_qwfi[2][192];   // packed int8 dw weight rows [c][3] = (w0,w1,w2,0)

// ---------------- prep: weight quantization + amax reset ---------------------
__global__ void k_prep(const float* __restrict__ wp1, const float* __restrict__ wf1,
                       const float* __restrict__ wp2, const float* __restrict__ wf2)
{
    int b = blockIdx.x;   // 0:wp1 1:wf1 2:wp2 3:wf2
    const float* w = (b == 0) ? wp1 : (b == 1) ? wf1 : (b == 2) ? wp2 : wf2;
    int n = (b & 1) ? 576 : 4096;

    __shared__ float red[256];
    float m = 0.f;
    for (int i = threadIdx.x; i < n; i += 256) m = fmaxf(m, fabsf(w[i]));
    red[threadIdx.x] = m;
    __syncthreads();
    for (int s = 128; s > 0; s >>= 1) {
        if (threadIdx.x < s) red[threadIdx.x] = fmaxf(red[threadIdx.x], red[threadIdx.x + s]);
        __syncthreads();
    }
    __shared__ float s_scale;
    if (threadIdx.x == 0) {
        float sc = red[0] / 7.0f + 1e-12f;
        g_wscale[b] = sc;
        s_scale = sc;
        if (b == 0) { g_amax[0] = 0u; g_amax[1] = 0u; g_amax[2] = 0u; g_amax[3] = 0u; }
    }
    __syncthreads();
    float sc = s_scale;

    if (b & 1) {
        // depthwise: pack integer weight rows (w0,w1,w2,0) as int8x4
        for (int i = threadIdx.x; i < 192; i += 256) {
            const float* wr = w + (i / 3) * 9 + (i % 3) * 3;
            int q0 = (int)fminf(fmaxf(rintf(wr[0] / sc), -7.f), 7.f);
            int q1 = (int)fminf(fmaxf(rintf(wr[1] / sc), -7.f), 7.f);
            int q2 = (int)fminf(fmaxf(rintf(wr[2] / sc), -7.f), 7.f);
            g_qwfi[b >> 1][i] = (q0 & 0xFF) | ((q1 & 0xFF) << 8) | ((q2 & 0xFF) << 16);
        }
    } else {
        for (int i = threadIdx.x; i < 1024; i += 256) {
            int word = 0;
            #pragma unroll
            for (int j = 0; j < 4; j++) {
                float q = fminf(fmaxf(rintf(w[i * 4 + j] / sc), -7.f), 7.f);
                int qi = (int)q;
                word |= (qi & 0xFF) << (8 * j);
            }
            g_qwp[b >> 1][i] = word;
        }
    }
}

// ---------------- abs-max of x ----------------------------------------------
__global__ void __launch_bounds__(256) k_absmax(const float4* __restrict__ x, int nvec)
{
    float m = 0.f;
    for (int i = blockIdx.x * blockDim.x + threadIdx.x; i < nvec; i += gridDim.x * blockDim.x) {
        float4 v = x[i];
        m = fmaxf(m, fmaxf(fmaxf(fabsf(v.x), fabsf(v.y)), fmaxf(fabsf(v.z), fabsf(v.w))));
    }
    #pragma unroll
    for (int off = 16; off; off >>= 1) m = fmaxf(m, __shfl_xor_sync(0xFFFFFFFFu, m, off));
    __shared__ float wm[8];
    int lane = threadIdx.x & 31, wid = threadIdx.x >> 5;
    if (lane == 0) wm[wid] = m;
    __syncthreads();
    if (threadIdx.x == 0) {
        float mm = wm[0];
        #pragma unroll
        for (int i = 1; i < 8; i++) mm = fmaxf(mm, wm[i]);
        atomicMax(&g_amax[0], __float_as_uint(mm));
    }
}

// ---------------- pointwise 1x1 conv (dp4a), 4 pixels/thread -----------------
// WHICH 0: in = x (fp32),   out = bufA (half), amax 0 -> 1
// WHICH 1: in = bufB (half), out = bufA (half), amax 2 -> 3
template<int WHICH>
__global__ void __launch_bounds__(128) k_pw(const float* __restrict__ x32)
{
    __shared__ __align__(16) int ws[1024];
    for (int i = threadIdx.x; i < 1024; i += 128) ws[i] = g_qwp[WHICH][i];
    __syncthreads();

    float in_max = __uint_as_float(g_amax[WHICH * 2]);
    float s_in = in_max * (1.0f / 127.0f) + 1e-12f;
    float inv  = 1.0f / s_in;
    float osc  = s_in * g_wscale[WHICH * 2];

    unsigned p  = (blockIdx.x * 128u + threadIdx.x) * 4u;   // first of 4 pixels
    unsigned b  = p >> 16;
    unsigned hw = p & 0xFFFFu;
    unsigned base = b * (CCH * HW) + hw;

    int xq0[16], xq1[16], xq2[16], xq3[16];
    #pragma unroll
    for (int k = 0; k < 16; k++) {
        int w0 = 0, w1 = 0, w2 = 0, w3 = 0;
        #pragma unroll
        for (int j = 0; j < 4; j++) {
            unsigned ci = 4 * k + j;
            float v0, v1, v2, v3;
            if (WHICH == 0) {
                float4 v = *reinterpret_cast<const float4*>(x32 + base + ci * HW);
                v0 = v.x; v1 = v.y; v2 = v.z; v3 = v.w;
            } else {
                uint2 raw = *reinterpret_cast<const uint2*>(g_bufB + base + ci * HW);
                float2 f01 = __half22float2(*reinterpret_cast<__half2*>(&raw.x));
                float2 f23 = __half22float2(*reinterpret_cast<__half2*>(&raw.y));
                v0 = f01.x; v1 = f01.y; v2 = f23.x; v3 = f23.y;
            }
            w0 |= (__float2int_rn(v0 * inv) & 0xFF) << (8 * j);
            w1 |= (__float2int_rn(v1 * inv) & 0xFF) << (8 * j);
            w2 |= (__float2int_rn(v2 * inv) & 0xFF) << (8 * j);
            w3 |= (__float2int_rn(v3 * inv) & 0xFF) << (8 * j);
        }
        xq0[k] = w0; xq1[k] = w1; xq2[k] = w2; xq3[k] = w3;
    }

    float lmax = 0.f;
    #pragma unroll 2
    for (int co = 0; co < 64; co++) {
        int a0 = 0, a1 = 0, a2 = 0, a3 = 0;
        #pragma unroll
        for (int k4 = 0; k4 < 4; k4++) {
            int4 w4 = *reinterpret_cast<const int4*>(&ws[co * 16 + k4 * 4]);
            a0 = __dp4a(w4.x, xq0[4 * k4 + 0], a0);
            a0 = __dp4a(w4.y, xq0[4 * k4 + 1], a0);
            a0 = __dp4a(w4.z, xq0[4 * k4 + 2], a0);
            a0 = __dp4a(w4.w, xq0[4 * k4 + 3], a0);
            a1 = __dp4a(w4.x, xq1[4 * k4 + 0], a1);
            a1 = __dp4a(w4.y, xq1[4 * k4 + 1], a1);
            a1 = __dp4a(w4.z, xq1[4 * k4 + 2], a1);
            a1 = __dp4a(w4.w, xq1[4 * k4 + 3], a1);
            a2 = __dp4a(w4.x, xq2[4 * k4 + 0], a2);
            a2 = __dp4a(w4.y, xq2[4 * k4 + 1], a2);
            a2 = __dp4a(w4.z, xq2[4 * k4 + 2], a2);
            a2 = __dp4a(w4.w, xq2[4 * k4 + 3], a2);
            a3 = __dp4a(w4.x, xq3[4 * k4 + 0], a3);
            a3 = __dp4a(w4.y, xq3[4 * k4 + 1], a3);
            a3 = __dp4a(w4.z, xq3[4 * k4 + 2], a3);
            a3 = __dp4a(w4.w, xq3[4 * k4 + 3], a3);
        }
        float y0 = (float)a0 * osc;
        float y1 = (float)a1 * osc;
        float y2 = (float)a2 * osc;
        float y3 = (float)a3 * osc;
        lmax = fmaxf(lmax, fmaxf(fmaxf(fabsf(y0), fabsf(y1)), fmaxf(fabsf(y2), fabsf(y3))));
        __half2 h01 = __floats2half2_rn(y0, y1);
        __half2 h23 = __floats2half2_rn(y2, y3);
        uint2 st;
        st.x = *reinterpret_cast<unsigned*>(&h01);
        st.y = *reinterpret_cast<unsigned*>(&h23);
        *reinterpret_cast<uint2*>(g_bufA + base + (unsigned)co * HW) = st;
    }

    #pragma unroll
    for (int off = 16; off; off >>= 1) lmax = fmaxf(lmax, __shfl_xor_sync(0xFFFFFFFFu, lmax, off));
    __shared__ float wm[4];
    int lane = threadIdx.x & 31, wid = threadIdx.x >> 5;
    if (lane == 0) wm[wid] = lmax;
    __syncthreads();
    if (threadIdx.x == 0) {
        float mm = fmaxf(fmaxf(wm[0], wm[1]), fmaxf(wm[2], wm[3]));
        atomicMax(&g_amax[WHICH * 2 + 1], __float_as_uint(mm));
    }
}

// ---------------- depthwise 3x3 (exact int8 dp4a) + PReLU (+residual) --------
// WHICH 0: bufA(half) -> bufB(half), amax_in [1], fused amax_out [2]
// WHICH 1: bufA(half) -> dout(fp32) + residual xres, amax_in [3]
// Block: 128 thr = 4 warps; each warp spans a full 256-col row (8 cols/lane),
// processes 8 output rows. Grid: 1024 (b*c) x 8 strips of 32 rows.
template<int WHICH>
__global__ void __launch_bounds__(128) k_dw(const float* __restrict__ xres,
                                            float* __restrict__ dout,
                                            const float* __restrict__ alpha)
{
    int bc    = blockIdx.x >> 3;     // 0..1023
    int strip = blockIdx.x & 7;
    int c     = bc & 63;
    int warp  = threadIdx.x >> 5;
    int lane  = threadIdx.x & 31;
    int rbase = strip * 32 + warp * 8;
    int col0  = lane * 8;

    float in_max = __uint_as_float(g_amax[WHICH == 0 ? 1 : 3]);
    float s_in = in_max * (1.0f / 127.0f) + 1e-12f;
    float inv  = 1.0f / s_in;
    float osc  = s_in * g_wscale[WHICH == 0 ? 1 : 3];   // int acc -> fp value

    int wr0 = g_qwfi[WHICH][c * 3 + 0];
    int wr1 = g_qwfi[WHICH][c * 3 + 1];
    int wr2 = g_qwfi[WHICH][c * 3 + 2];
    float a = alpha[c];

    const __half* in = g_bufA + (unsigned)bc * HW;
    int accT[8], accM[8];
    #pragma unroll
    for (int j = 0; j < 8; j++) { accT[j] = 0; accM[j] = 0; }
    float lmax = 0.f;

    #pragma unroll
    for (int k = 0; k < 10; k++) {
        int rr = rbase - 1 + k;          // warp-uniform input row
        unsigned wA = 0, wB = 0;
        if (rr >= 0 && rr < 256) {
            uint4 raw = *reinterpret_cast<const uint4*>(in + rr * 256 + col0);
            float2 f0 = __half22float2(*reinterpret_cast<__half2*>(&raw.x));
            float2 f1 = __half22float2(*reinterpret_cast<__half2*>(&raw.y));
            float2 f2 = __half22float2(*reinterpret_cast<__half2*>(&raw.z));
            float2 f3 = __half22float2(*reinterpret_cast<__half2*>(&raw.w));
            int q0 = __float2int_rn(f0.x * inv), q1 = __float2int_rn(f0.y * inv);
            int q2 = __float2int_rn(f1.x * inv), q3 = __float2int_rn(f1.y * inv);
            int q4 = __float2int_rn(f2.x * inv), q5 = __float2int_rn(f2.y * inv);
            int q6 = __float2int_rn(f3.x * inv), q7 = __float2int_rn(f3.y * inv);
            wA = __byte_perm(__byte_perm(q0, q1, 0x0040),
                             __byte_perm(q2, q3, 0x0040), 0x5410);
            wB = __byte_perm(__byte_perm(q4, q5, 0x0040),
                             __byte_perm(q6, q7, 0x0040), 0x5410);
        }
        unsigned wPrev = __shfl_up_sync(0xFFFFFFFFu, wB, 1);
        unsigned wNext = __shfl_down_sync(0xFFFFFFFFu, wA, 1);
        if (lane == 0)  wPrev = 0;    // image left edge
        if (lane == 31) wNext = 0;    // image right edge

        // 8 sliding windows: bytes (q[j-1], q[j], q[j+1], X) — X hits weight 0
        unsigned win[8];
        win[0] = __byte_perm(wPrev, wA, 0x0543);
        win[1] = wA;
        win[2] = __byte_perm(wA, wB, 0x4321);
        win[3] = __byte_perm(wA, wB, 0x5432);
        win[4] = __byte_perm(wA, wB, 0x6543);
        win[5] = wB;
        win[6] = __byte_perm(wB, wNext, 0x4321);
        win[7] = __byte_perm(wB, wNext, 0x5432);

        if (k >= 2) {
            int ro = rbase + k - 2;
            unsigned off = (unsigned)bc * HW + (unsigned)(ro * 256 + col0);
            float y[8];
            #pragma unroll
            for (int j = 0; j < 8; j++) {
                int acc = __dp4a((int)win[j], wr2, accM[j]);
                float v = (float)acc * osc;
                y[j] = (v > 0.f) ? v : a * v;
            }
            if (WHICH == 0) {
                #pragma unroll
                for (int j = 0; j < 8; j++) lmax = fmaxf(lmax, fabsf(y[j]));
                uint4 st;
                __half2 h0 = __floats2half2_rn(y[0], y[1]);
                __half2 h1 = __floats2half2_rn(y[2], y[3]);
                __half2 h2 = __floats2half2_rn(y[4], y[5]);
                __half2 h3 = __floats2half2_rn(y[6], y[7]);
                st.x = *reinterpret_cast<unsigned*>(&h0);
                st.y = *reinterpret_cast<unsigned*>(&h1);
                st.z = *reinterpret_cast<unsigned*>(&h2);
                st.w = *reinterpret_cast<unsigned*>(&h3);
                *reinterpret_cast<uint4*>(g_bufB + off) = st;
            } else {
                float4 r0 = *reinterpret_cast<const float4*>(xres + off);
                float4 r1 = *reinterpret_cast<const float4*>(xres + off + 4);
                float4 o0, o1;
                o0.x = y[0] + r0.x; o0.y = y[1] + r0.y;
                o0.z = y[2] + r0.z; o0.w = y[3] + r0.w;
                o1.x = y[4] + r1.x; o1.y = y[5] + r1.y;
                o1.z = y[6] + r1.z; o1.w = y[7] + r1.w;
                *reinterpret_cast<float4*>(dout + off)     = o0;
                *reinterpret_cast<float4*>(dout + off + 4) = o1;
            }
        }
        #pragma unroll
        for (int j = 0; j < 8; j++) {
            accM[j] = __dp4a((int)win[j], wr1, accT[j]);
            accT[j] = __dp4a((int)win[j], wr0, 0);
        }
    }

    if (WHICH == 0) {
        #pragma unroll
        for (int off = 16; off; off >>= 1) lmax = fmaxf(lmax, __shfl_xor_sync(0xFFFFFFFFu, lmax, off));
        __shared__ float wm[4];
        if (lane == 0) wm[warp] = lmax;
        __syncthreads();
        if (threadIdx.x == 0) {
            float mm = fmaxf(fmaxf(wm[0], wm[1]), fmaxf(wm[2], wm[3]));
            atomicMax(&g_amax[2], __float_as_uint(mm));
        }
    }
}

// ---------------- launch ------------------------------------------------------
extern "C" void kernel_launch(void* const* d_in, const int* in_sizes, int n_in,
                              void* d_out, int out_size)
{
    const float* x      = (const float*)d_in[0];
    const float* w_p1   = (const float*)d_in[1];
    const float* w_f1   = (const float*)d_in[2];
    const float* w_p2   = (const float*)d_in[3];
    const float* w_f2   = (const float*)d_in[4];
    const float* alpha1 = (const float*)d_in[5];
    const float* alpha2 = (const float*)d_in[6];
    float* out = (float*)d_out;

    k_prep<<<4, 256>>>(w_p1, w_f1, w_p2, w_f2);
    k_absmax<<<2048, 256>>>((const float4*)x, NTOT / 4);

    k_pw<0><<<NPIX / 512, 128>>>(x);                    // x -> bufA, amax y1
    k_dw<0><<<8192, 128>>>(nullptr, nullptr, alpha1);   // bufA -> bufB, amax y3
    k_pw<1><<<NPIX / 512, 128>>>(nullptr);              // bufB -> bufA, amax y4
    k_dw<1><<<8192, 128>>>(x, out, alpha2);             // bufA -> out (+x)
}

// round 5
// speedup vs baseline: 2.0726x; 1.0087x over previous
#include <cuda_runtime.h>
#include <cuda_fp16.h>
#include <cstdint>

#define HW    65536
#define CCH   64
#define NPIX  (16 * HW)            // 1,048,576 pixels
#define NTOT  (16 * CCH * HW)      // 67,108,864 elements

// ---------------- device scratch (allocation-free) ---------------------------
__device__ __half   g_bufA[NTOT];
__device__ __half   g_bufB[NTOT];
__device__ __half   g_bufC[NTOT];     // fp16 shadow of x
__device__ unsigned g_amax[4];        // abs-max bits of: x, y1, y3, y4
__device__ float    g_wscale[4];      // scales of: w_p1, w_f1, w_p2, w_f2
__device__ int      g_qwp[2][1024];   // packed int8 pointwise weights [co][ci/4]
__device__ int      g_qwfi[2][192];   // packed int8 dw weight rows [c][3] = (w0,w1,w2,0)

// ---------------- prep: weight quantization + amax reset ---------------------
__global__ void k_prep(const float* __restrict__ wp1, const float* __restrict__ wf1,
                       const float* __restrict__ wp2, const float* __restrict__ wf2)
{
    int b = blockIdx.x;   // 0:wp1 1:wf1 2:wp2 3:wf2
    const float* w = (b == 0) ? wp1 : (b == 1) ? wf1 : (b == 2) ? wp2 : wf2;
    int n = (b & 1) ? 576 : 4096;

    __shared__ float red[256];
    float m = 0.f;
    for (int i = threadIdx.x; i < n; i += 256) m = fmaxf(m, fabsf(w[i]));
    red[threadIdx.x] = m;
    __syncthreads();
    for (int s = 128; s > 0; s >>= 1) {
        if (threadIdx.x < s) red[threadIdx.x] = fmaxf(red[threadIdx.x], red[threadIdx.x + s]);
        __syncthreads();
    }
    __shared__ float s_scale;
    if (threadIdx.x == 0) {
        float sc = red[0] / 7.0f + 1e-12f;
        g_wscale[b] = sc;
        s_scale = sc;
        if (b == 0) { g_amax[0] = 0u; g_amax[1] = 0u; g_amax[2] = 0u; g_amax[3] = 0u; }
    }
    __syncthreads();
    float sc = s_scale;

    if (b & 1) {
        // depthwise: pack integer weight rows (w0,w1,w2,0) as int8x4
        for (int i = threadIdx.x; i < 192; i += 256) {
            const float* wr = w + (i / 3) * 9 + (i % 3) * 3;
            int q0 = (int)fminf(fmaxf(rintf(wr[0] / sc), -7.f), 7.f);
            int q1 = (int)fminf(fmaxf(rintf(wr[1] / sc), -7.f), 7.f);
            int q2 = (int)fminf(fmaxf(rintf(wr[2] / sc), -7.f), 7.f);
            g_qwfi[b >> 1][i] = (q0 & 0xFF) | ((q1 & 0xFF) << 8) | ((q2 & 0xFF) << 16);
        }
    } else {
        for (int i = threadIdx.x; i < 1024; i += 256) {
            int word = 0;
            #pragma unroll
            for (int j = 0; j < 4; j++) {
                float q = fminf(fmaxf(rintf(w[i * 4 + j] / sc), -7.f), 7.f);
                int qi = (int)q;
                word |= (qi & 0xFF) << (8 * j);
            }
            g_qwp[b >> 1][i] = word;
        }
    }
}

// ---------------- abs-max of x + fp16 shadow copy -----------------------------
__global__ void __launch_bounds__(256) k_absmax(const float4* __restrict__ x, int nvec)
{
    uint2* __restrict__ c16 = reinterpret_cast<uint2*>(g_bufC);
    float m = 0.f;
    for (int i = blockIdx.x * blockDim.x + threadIdx.x; i < nvec; i += gridDim.x * blockDim.x) {
        float4 v = x[i];
        __half2 h01 = __floats2half2_rn(v.x, v.y);
        __half2 h23 = __floats2half2_rn(v.z, v.w);
        uint2 st;
        st.x = *reinterpret_cast<unsigned*>(&h01);
        st.y = *reinterpret_cast<unsigned*>(&h23);
        c16[i] = st;
        m = fmaxf(m, fmaxf(fmaxf(fabsf(v.x), fabsf(v.y)), fmaxf(fabsf(v.z), fabsf(v.w))));
    }
    #pragma unroll
    for (int off = 16; off; off >>= 1) m = fmaxf(m, __shfl_xor_sync(0xFFFFFFFFu, m, off));
    __shared__ float wm[8];
    int lane = threadIdx.x & 31, wid = threadIdx.x >> 5;
    if (lane == 0) wm[wid] = m;
    __syncthreads();
    if (threadIdx.x == 0) {
        float mm = wm[0];
        #pragma unroll
        for (int i = 1; i < 8; i++) mm = fmaxf(mm, wm[i]);
        atomicMax(&g_amax[0], __float_as_uint(mm));
    }
}

// ---------------- pointwise 1x1 conv (dp4a), 4 pixels/thread -----------------
// WHICH 0: in = bufC (half x), out = bufA (half), amax 0 -> 1
// WHICH 1: in = bufB (half),   out = bufA (half), amax 2 -> 3
template<int WHICH>
__global__ void __launch_bounds__(128) k_pw()
{
    __shared__ __align__(16) int ws[1024];
    for (int i = threadIdx.x; i < 1024; i += 128) ws[i] = g_qwp[WHICH][i];
    __syncthreads();

    float in_max = __uint_as_float(g_amax[WHICH * 2]);
    float s_in = in_max * (1.0f / 127.0f) + 1e-12f;
    float inv  = 1.0f / s_in;
    float osc  = s_in * g_wscale[WHICH * 2];

    unsigned p  = (blockIdx.x * 128u + threadIdx.x) * 4u;   // first of 4 pixels
    unsigned b  = p >> 16;
    unsigned hw = p & 0xFFFFu;
    unsigned base = b * (CCH * HW) + hw;
    const __half* in = (WHICH == 0) ? g_bufC : g_bufB;

    int xq0[16], xq1[16], xq2[16], xq3[16];
    #pragma unroll
    for (int k = 0; k < 16; k++) {
        int w0 = 0, w1 = 0, w2 = 0, w3 = 0;
        #pragma unroll
        for (int j = 0; j < 4; j++) {
            unsigned ci = 4 * k + j;
            uint2 raw = *reinterpret_cast<const uint2*>(in + base + ci * HW);
            float2 f01 = __half22float2(*reinterpret_cast<__half2*>(&raw.x));
            float2 f23 = __half22float2(*reinterpret_cast<__half2*>(&raw.y));
            w0 |= (__float2int_rn(f01.x * inv) & 0xFF) << (8 * j);
            w1 |= (__float2int_rn(f01.y * inv) & 0xFF) << (8 * j);
            w2 |= (__float2int_rn(f23.x * inv) & 0xFF) << (8 * j);
            w3 |= (__float2int_rn(f23.y * inv) & 0xFF) << (8 * j);
        }
        xq0[k] = w0; xq1[k] = w1; xq2[k] = w2; xq3[k] = w3;
    }

    float lmax = 0.f;
    #pragma unroll 2
    for (int co = 0; co < 64; co++) {
        int a0 = 0, a1 = 0, a2 = 0, a3 = 0;
        #pragma unroll
        for (int k4 = 0; k4 < 4; k4++) {
            int4 w4 = *reinterpret_cast<const int4*>(&ws[co * 16 + k4 * 4]);
            a0 = __dp4a(w4.x, xq0[4 * k4 + 0], a0);
            a0 = __dp4a(w4.y, xq0[4 * k4 + 1], a0);
            a0 = __dp4a(w4.z, xq0[4 * k4 + 2], a0);
            a0 = __dp4a(w4.w, xq0[4 * k4 + 3], a0);
            a1 = __dp4a(w4.x, xq1[4 * k4 + 0], a1);
            a1 = __dp4a(w4.y, xq1[4 * k4 + 1], a1);
            a1 = __dp4a(w4.z, xq1[4 * k4 + 2], a1);
            a1 = __dp4a(w4.w, xq1[4 * k4 + 3], a1);
            a2 = __dp4a(w4.x, xq2[4 * k4 + 0], a2);
            a2 = __dp4a(w4.y, xq2[4 * k4 + 1], a2);
            a2 = __dp4a(w4.z, xq2[4 * k4 + 2], a2);
            a2 = __dp4a(w4.w, xq2[4 * k4 + 3], a2);
            a3 = __dp4a(w4.x, xq3[4 * k4 + 0], a3);
            a3 = __dp4a(w4.y, xq3[4 * k4 + 1], a3);
            a3 = __dp4a(w4.z, xq3[4 * k4 + 2], a3);
            a3 = __dp4a(w4.w, xq3[4 * k4 + 3], a3);
        }
        float y0 = (float)a0 * osc;
        float y1 = (float)a1 * osc;
        float y2 = (float)a2 * osc;
        float y3 = (float)a3 * osc;
        lmax = fmaxf(lmax, fmaxf(fmaxf(fabsf(y0), fabsf(y1)), fmaxf(fabsf(y2), fabsf(y3))));
        __half2 h01 = __floats2half2_rn(y0, y1);
        __half2 h23 = __floats2half2_rn(y2, y3);
        uint2 st;
        st.x = *reinterpret_cast<unsigned*>(&h01);
        st.y = *reinterpret_cast<unsigned*>(&h23);
        *reinterpret_cast<uint2*>(g_bufA + base + (unsigned)co * HW) = st;
    }

    #pragma unroll
    for (int off = 16; off; off >>= 1) lmax = fmaxf(lmax, __shfl_xor_sync(0xFFFFFFFFu, lmax, off));
    __shared__ float wm[4];
    int lane = threadIdx.x & 31, wid = threadIdx.x >> 5;
    if (lane == 0) wm[wid] = lmax;
    __syncthreads();
    if (threadIdx.x == 0) {
        float mm = fmaxf(fmaxf(wm[0], wm[1]), fmaxf(wm[2], wm[3]));
        atomicMax(&g_amax[WHICH * 2 + 1], __float_as_uint(mm));
    }
}

// ---------------- depthwise 3x3 (exact int8 dp4a) + PReLU (+residual) --------
// WHICH 0: bufA(half) -> bufB(half), amax_in [1], fused amax_out [2]
// WHICH 1: bufA(half) -> dout(fp32) + residual bufC(half x), amax_in [3]
template<int WHICH>
__global__ void __launch_bounds__(128) k_dw(float* __restrict__ dout,
                                            const float* __restrict__ alpha)
{
    int bc    = blockIdx.x >> 3;     // 0..1023
    int strip = blockIdx.x & 7;
    int c     = bc & 63;
    int warp  = threadIdx.x >> 5;
    int lane  = threadIdx.x & 31;
    int rbase = strip * 32 + warp * 8;
    int col0  = lane * 8;

    float in_max = __uint_as_float(g_amax[WHICH == 0 ? 1 : 3]);
    float s_in = in_max * (1.0f / 127.0f) + 1e-12f;
    float inv  = 1.0f / s_in;
    float osc  = s_in * g_wscale[WHICH == 0 ? 1 : 3];   // int acc -> fp value

    int wr0 = g_qwfi[WHICH][c * 3 + 0];
    int wr1 = g_qwfi[WHICH][c * 3 + 1];
    int wr2 = g_qwfi[WHICH][c * 3 + 2];
    float a = alpha[c];

    const __half* in = g_bufA + (unsigned)bc * HW;
    int accT[8], accM[8];
    #pragma unroll
    for (int j = 0; j < 8; j++) { accT[j] = 0; accM[j] = 0; }
    float lmax = 0.f;

    #pragma unroll
    for (int k = 0; k < 10; k++) {
        int rr = rbase - 1 + k;          // warp-uniform input row
        unsigned wA = 0, wB = 0;
        if (rr >= 0 && rr < 256) {
            uint4 raw = *reinterpret_cast<const uint4*>(in + rr * 256 + col0);
            float2 f0 = __half22float2(*reinterpret_cast<__half2*>(&raw.x));
            float2 f1 = __half22float2(*reinterpret_cast<__half2*>(&raw.y));
            float2 f2 = __half22float2(*reinterpret_cast<__half2*>(&raw.z));
            float2 f3 = __half22float2(*reinterpret_cast<__half2*>(&raw.w));
            int q0 = __float2int_rn(f0.x * inv), q1 = __float2int_rn(f0.y * inv);
            int q2 = __float2int_rn(f1.x * inv), q3 = __float2int_rn(f1.y * inv);
            int q4 = __float2int_rn(f2.x * inv), q5 = __float2int_rn(f2.y * inv);
            int q6 = __float2int_rn(f3.x * inv), q7 = __float2int_rn(f3.y * inv);
            wA = __byte_perm(__byte_perm(q0, q1, 0x0040),
                             __byte_perm(q2, q3, 0x0040), 0x5410);
            wB = __byte_perm(__byte_perm(q4, q5, 0x0040),
                             __byte_perm(q6, q7, 0x0040), 0x5410);
        }
        unsigned wPrev = __shfl_up_sync(0xFFFFFFFFu, wB, 1);
        unsigned wNext = __shfl_down_sync(0xFFFFFFFFu, wA, 1);
        if (lane == 0)  wPrev = 0;    // image left edge
        if (lane == 31) wNext = 0;    // image right edge

        // 8 sliding windows: bytes (q[j-1], q[j], q[j+1], X) — X hits weight 0
        unsigned win[8];
        win[0] = __byte_perm(wPrev, wA, 0x0543);
        win[1] = wA;
        win[2] = __byte_perm(wA, wB, 0x4321);
        win[3] = __byte_perm(wA, wB, 0x5432);
        win[4] = __byte_perm(wA, wB, 0x6543);
        win[5] = wB;
        win[6] = __byte_perm(wB, wNext, 0x4321);
        win[7] = __byte_perm(wB, wNext, 0x5432);

        if (k >= 2) {
            int ro = rbase + k - 2;
            unsigned off = (unsigned)bc * HW + (unsigned)(ro * 256 + col0);
            float y[8];
            #pragma unroll
            for (int j = 0; j < 8; j++) {
                int acc = __dp4a((int)win[j], wr2, accM[j]);
                float v = (float)acc * osc;
                y[j] = (v > 0.f) ? v : a * v;
            }
            if (WHICH == 0) {
                #pragma unroll
                for (int j = 0; j < 8; j++) lmax = fmaxf(lmax, fabsf(y[j]));
                uint4 st;
                __half2 h0 = __floats2half2_rn(y[0], y[1]);
                __half2 h1 = __floats2half2_rn(y[2], y[3]);
                __half2 h2 = __floats2half2_rn(y[4], y[5]);
                __half2 h3 = __floats2half2_rn(y[6], y[7]);
                st.x = *reinterpret_cast<unsigned*>(&h0);
                st.y = *reinterpret_cast<unsigned*>(&h1);
                st.z = *reinterpret_cast<unsigned*>(&h2);
                st.w = *reinterpret_cast<unsigned*>(&h3);
                *reinterpret_cast<uint4*>(g_bufB + off) = st;
            } else {
                uint4 rr16 = *reinterpret_cast<const uint4*>(g_bufC + off);
                float2 r0 = __half22float2(*reinterpret_cast<__half2*>(&rr16.x));
                float2 r1 = __half22float2(*reinterpret_cast<__half2*>(&rr16.y));
                float2 r2 = __half22float2(*reinterpret_cast<__half2*>(&rr16.z));
                float2 r3 = __half22float2(*reinterpret_cast<__half2*>(&rr16.w));
                float4 o0, o1;
                o0.x = y[0] + r0.x; o0.y = y[1] + r0.y;
                o0.z = y[2] + r1.x; o0.w = y[3] + r1.y;
                o1.x = y[4] + r2.x; o1.y = y[5] + r2.y;
                o1.z = y[6] + r3.x; o1.w = y[7] + r3.y;
                *reinterpret_cast<float4*>(dout + off)     = o0;
                *reinterpret_cast<float4*>(dout + off + 4) = o1;
            }
        }
        #pragma unroll
        for (int j = 0; j < 8; j++) {
            accM[j] = __dp4a((int)win[j], wr1, accT[j]);
            accT[j] = __dp4a((int)win[j], wr0, 0);
        }
    }

    if (WHICH == 0) {
        #pragma unroll
        for (int off = 16; off; off >>= 1) lmax = fmaxf(lmax, __shfl_xor_sync(0xFFFFFFFFu, lmax, off));
        __shared__ float wm[4];
        if (lane == 0) wm[warp] = lmax;
        __syncthreads();
        if (threadIdx.x == 0) {
            float mm = fmaxf(fmaxf(wm[0], wm[1]), fmaxf(wm[2], wm[3]));
            atomicMax(&g_amax[2], __float_as_uint(mm));
        }
    }
}

// ---------------- launch ------------------------------------------------------
extern "C" void kernel_launch(void* const* d_in, const int* in_sizes, int n_in,
                              void* d_out, int out_size)
{
    const float* x      = (const float*)d_in[0];
    const float* w_p1   = (const float*)d_in[1];
    const float* w_f1   = (const float*)d_in[2];
    const float* w_p2   = (const float*)d_in[3];
    const float* w_f2   = (const float*)d_in[4];
    const float* alpha1 = (const float*)d_in[5];
    const float* alpha2 = (const float*)d_in[6];
    float* out = (float*)d_out;

    k_prep<<<4, 256>>>(w_p1, w_f1, w_p2, w_f2);
    k_absmax<<<2048, 256>>>((const float4*)x, NTOT / 4);   // amax x + x16 copy

    k_pw<0><<<NPIX / 512, 128>>>();              // bufC -> bufA, amax y1
    k_dw<0><<<8192, 128>>>(nullptr, alpha1);     // bufA -> bufB, amax y3
    k_pw<1><<<NPIX / 512, 128>>>();              // bufB -> bufA, amax y4
    k_dw<1><<<8192, 128>>>(out, alpha2);         // bufA -> out (+x16)
}